// round 5
// baseline (speedup 1.0000x reference)
#include <cuda_runtime.h>
#include <cstdint>

typedef uint32_t u32;

// ------------------------------------------------------------------
// LISTA fused, mma.sync tf32, round 5.
//   B    = We @ x            (K=64)
//   z    = softshrink(B, th0)
//   3x:  z = softshrink(B + S[i] @ z, th[i+1])
//
// CTA = 128 px x 256 dict, 512 threads = 16 warps (4 dict x 4 px),
// warp tile 64d x 32px via m16n8k8 tf32. z tile pixel-major in smem
// (ldmatrix-friendly), B in registers, W chunks double-buffered.
// ------------------------------------------------------------------

#define WSTRIDE 36                       // floats per W row (32 k + pad)
#define ZSTRIDE 260                      // floats per Zt row (256 dict + pad)
#define W_FLOATS (256 * WSTRIDE)         // 9216 per buffer
#define W_BYTES  (W_FLOATS * 4)          // 36864
#define Z_FLOATS (128 * ZSTRIDE)         // 33280
#define SMEM_BYTES ((Z_FLOATS + 2 * W_FLOATS) * 4)   // 206848

__device__ __forceinline__ u32 smem_u32(const void* p) {
    u32 a;
    asm("{ .reg .u64 t; cvta.to.shared.u64 t, %1; cvt.u32.u64 %0, t; }"
        : "=r"(a) : "l"(p));
    return a;
}
__device__ __forceinline__ u32 f2tf32(float f) {
    u32 r; asm("cvt.rna.tf32.f32 %0, %1;" : "=r"(r) : "f"(f)); return r;
}
__device__ __forceinline__ float tf(float f) { return __uint_as_float(f2tf32(f)); }
__device__ __forceinline__ float sshrink(float f, float th) {
    return f - fminf(fmaxf(f, -th), th);
}
__device__ __forceinline__ void ldsm4(u32& r0, u32& r1, u32& r2, u32& r3, u32 addr) {
    asm volatile("ldmatrix.sync.aligned.m8n8.x4.shared.b16 {%0,%1,%2,%3}, [%4];"
                 : "=r"(r0), "=r"(r1), "=r"(r2), "=r"(r3) : "r"(addr));
}
__device__ __forceinline__ void mma8(float* c, const u32* a, u32 b0, u32 b1) {
    asm volatile(
        "mma.sync.aligned.m16n8k8.row.col.f32.tf32.tf32.f32 "
        "{%0,%1,%2,%3}, {%4,%5,%6,%7}, {%8,%9}, {%0,%1,%2,%3};"
        : "+f"(c[0]), "+f"(c[1]), "+f"(c[2]), "+f"(c[3])
        : "r"(a[0]), "r"(a[1]), "r"(a[2]), "r"(a[3]), "r"(b0), "r"(b1));
}

// D[256d x 128px] (+)= W @ z.  W gmem row-major [256][rs], NCH chunks of 32 k.
// Zt smem pixel-major [128][ZSTRIDE].  Double-buffered W staging.
template <int NCH>
__device__ __forceinline__ void run_gemm(const float* __restrict__ Wg, int rs,
                                         float* WsF, u32 wsb, u32 aBase, u32 bBase,
                                         float acc[4][4][4], int& gch, int tid)
{
    const int d    = tid >> 1;
    const int half = tid & 1;
    const float* wrow = Wg + (size_t)d * rs + half * 16;
    const int    woff = d * WSTRIDE + half * 16;

    float4 p[4];
#pragma unroll
    for (int j = 0; j < 4; j++)
        p[j] = *reinterpret_cast<const float4*>(wrow + j * 4);

    // stage chunk 0
    {
        float* dst = WsF + (gch & 1) * W_FLOATS + woff;
#pragma unroll
        for (int j = 0; j < 4; j++)
            *reinterpret_cast<float4*>(dst + j * 4) =
                make_float4(tf(p[j].x), tf(p[j].y), tf(p[j].z), tf(p[j].w));
    }
    if (NCH > 1) {
#pragma unroll
        for (int j = 0; j < 4; j++)
            p[j] = *reinterpret_cast<const float4*>(wrow + 32 + j * 4);
    }
    __syncthreads();   // chunk0 visible (also publishes z/x writes before this GEMM)

#pragma unroll 1
    for (int ch = 0; ch < NCH; ch++) {
        if (ch + 1 < NCH) {
            // stage next chunk into the other buffer (overlaps MMAs below)
            float* dst = WsF + ((gch + ch + 1) & 1) * W_FLOATS + woff;
#pragma unroll
            for (int j = 0; j < 4; j++)
                *reinterpret_cast<float4*>(dst + j * 4) =
                    make_float4(tf(p[j].x), tf(p[j].y), tf(p[j].z), tf(p[j].w));
            if (ch + 2 < NCH) {
#pragma unroll
                for (int j = 0; j < 4; j++)
                    p[j] = *reinterpret_cast<const float4*>(
                        wrow + (ch + 2) * 32 + j * 4);
            }
        }

        const u32 aBuf = wsb + ((gch + ch) & 1) * W_BYTES + aBase;
        const u32 bCol = bBase + (u32)(ch * 32) * 4;

#pragma unroll
        for (int ks = 0; ks < 4; ks++) {
            u32 a[4][4];
#pragma unroll
            for (int mt = 0; mt < 4; mt++)
                ldsm4(a[mt][0], a[mt][1], a[mt][2], a[mt][3],
                      aBuf + (u32)(mt * 16 * WSTRIDE + ks * 8) * 4);
            u32 bb[2][4];
#pragma unroll
            for (int pr = 0; pr < 2; pr++)
                ldsm4(bb[pr][0], bb[pr][1], bb[pr][2], bb[pr][3],
                      bCol + (u32)(pr * 16 * ZSTRIDE + ks * 8) * 4);
#pragma unroll
            for (int mt = 0; mt < 4; mt++)
#pragma unroll
                for (int nt = 0; nt < 4; nt++)
                    mma8(acc[mt][nt], a[mt], bb[nt >> 1][nt & 1],
                         bb[nt >> 1][(nt & 1) + 2]);
        }
        __syncthreads();   // chunk ch+1 visible / buffer (gch+ch)&1 reusable
    }
    gch += NCH;
}

__global__ void __launch_bounds__(512, 1)
lista_mma(const float* __restrict__ x,
          const float* __restrict__ We,
          const float* __restrict__ S,
          const float* __restrict__ th,
          float* __restrict__ out)
{
    extern __shared__ float smem[];
    float* Zt  = smem;                       // [128 px][ZSTRIDE]
    float* WsF = smem + Z_FLOATS;            // 2 x [256][WSTRIDE]

    const int tid  = threadIdx.x;
    const int lane = tid & 31;
    const int wid  = tid >> 5;
    const int wd   = wid & 3;                // dict group (64 d)
    const int wp   = wid >> 2;               // pixel group (32 px)

    const u32 ztb = smem_u32(Zt);
    const u32 wsb = smem_u32(WsF);
    // ldmatrix per-thread bases (byte offsets / addresses)
    const u32 aBase = (u32)((wd * 64 + (lane & 15)) * WSTRIDE + (lane >> 4) * 4) * 4;
    const u32 bBase = ztb +
        (u32)((wp * 32 + (lane & 15)) * ZSTRIDE + (lane >> 4) * 4) * 4;

    const int pix0 = blockIdx.x * 128;
    const int b    = pix0 >> 16;             // 65536 px per image
    const int hw0  = pix0 & 65535;

    const float th0 = __ldg(th + 0), th1 = __ldg(th + 1);
    const float th2 = __ldg(th + 2), th3 = __ldg(th + 3);

    // ---- stage x (tf32) into Zt cols 0..63 (pixel-major) ----
    {
        const float* xb = x + (size_t)b * 64 * 65536 + hw0;
#pragma unroll
        for (int e = 0; e < 16; e++) {
            const int idx = tid + e * 512;   // 8192 = 64c * 128px
            const int px  = idx & 127;
            const int c   = idx >> 7;
            Zt[px * ZSTRIDE + c] = tf(__ldg(xb + (size_t)c * 65536 + px));
        }
    }
    // visibility via run_gemm's first __syncthreads

    float acc[4][4][4];
#pragma unroll
    for (int mt = 0; mt < 4; mt++)
#pragma unroll
        for (int nt = 0; nt < 4; nt++)
#pragma unroll
            for (int r = 0; r < 4; r++) acc[mt][nt][r] = 0.0f;

    int gch = 0;

    // ---- GEMM0: B = We @ x  (K=64) ----
    run_gemm<2>(We, 64, WsF, wsb, aBase, bBase, acc, gch, tid);

    float bacc[4][4][4];
#pragma unroll
    for (int mt = 0; mt < 4; mt++)
#pragma unroll
        for (int nt = 0; nt < 4; nt++)
#pragma unroll
            for (int r = 0; r < 4; r++) bacc[mt][nt][r] = acc[mt][nt][r];

    // ---- z0 = softshrink(B, th0) -> Zt ----
#pragma unroll
    for (int mt = 0; mt < 4; mt++) {
        const int d0 = wd * 64 + mt * 16 + (lane >> 2);
#pragma unroll
        for (int nt = 0; nt < 4; nt++) {
            const int px0 = wp * 32 + nt * 8 + 2 * (lane & 3);
            float* z0 = Zt + px0 * ZSTRIDE;
            z0[d0]               = tf(sshrink(acc[mt][nt][0], th0));
            z0[ZSTRIDE + d0]     = tf(sshrink(acc[mt][nt][1], th0));
            z0[d0 + 8]           = tf(sshrink(acc[mt][nt][2], th0));
            z0[ZSTRIDE + d0 + 8] = tf(sshrink(acc[mt][nt][3], th0));
        }
    }

    // ---- 3 LISTA iterations ----
#pragma unroll 1
    for (int it = 0; it < 3; it++) {
#pragma unroll
        for (int mt = 0; mt < 4; mt++)
#pragma unroll
            for (int nt = 0; nt < 4; nt++)
#pragma unroll
                for (int r = 0; r < 4; r++) acc[mt][nt][r] = bacc[mt][nt][r];

        run_gemm<8>(S + (size_t)it * 65536, 256, WsF, wsb, aBase, bBase,
                    acc, gch, tid);

        const float theta = (it == 0) ? th1 : (it == 1) ? th2 : th3;

        if (it < 2) {
#pragma unroll
            for (int mt = 0; mt < 4; mt++) {
                const int d0 = wd * 64 + mt * 16 + (lane >> 2);
#pragma unroll
                for (int nt = 0; nt < 4; nt++) {
                    const int px0 = wp * 32 + nt * 8 + 2 * (lane & 3);
                    float* z0 = Zt + px0 * ZSTRIDE;
                    z0[d0]               = tf(sshrink(acc[mt][nt][0], theta));
                    z0[ZSTRIDE + d0]     = tf(sshrink(acc[mt][nt][1], theta));
                    z0[d0 + 8]           = tf(sshrink(acc[mt][nt][2], theta));
                    z0[ZSTRIDE + d0 + 8] = tf(sshrink(acc[mt][nt][3], theta));
                }
            }
        } else {
            // final: out = softshrink(B + feat) straight to gmem
            float* ob = out + (size_t)b * 256 * 65536 + hw0;
#pragma unroll
            for (int mt = 0; mt < 4; mt++) {
                const int d0 = wd * 64 + mt * 16 + (lane >> 2);
#pragma unroll
                for (int nt = 0; nt < 4; nt++) {
                    const int px0 = wp * 32 + nt * 8 + 2 * (lane & 3);
                    *reinterpret_cast<float2*>(ob + (size_t)d0 * 65536 + px0) =
                        make_float2(sshrink(acc[mt][nt][0], theta),
                                    sshrink(acc[mt][nt][1], theta));
                    *reinterpret_cast<float2*>(ob + (size_t)(d0 + 8) * 65536 + px0) =
                        make_float2(sshrink(acc[mt][nt][2], theta),
                                    sshrink(acc[mt][nt][3], theta));
                }
            }
        }
    }
}

extern "C" void kernel_launch(void* const* d_in, const int* in_sizes, int n_in,
                              void* d_out, int out_size)
{
    (void)in_sizes; (void)n_in; (void)out_size;
    const float* x  = (const float*)d_in[0];
    const float* We = (const float*)d_in[1];
    const float* S  = (const float*)d_in[2];
    const float* th = (const float*)d_in[3];
    float* out      = (float*)d_out;

    cudaFuncSetAttribute(lista_mma, cudaFuncAttributeMaxDynamicSharedMemorySize,
                         SMEM_BYTES);
    lista_mma<<<2048, 512, SMEM_BYTES>>>(x, We, S, th, out);
}

// round 6
// speedup vs baseline: 1.0145x; 1.0145x over previous
#include <cuda_runtime.h>
#include <cstdint>

typedef uint32_t u32;

// ------------------------------------------------------------------
// LISTA fused, mma.sync tf32, round 6.
//   B    = We @ x            (K=64, recomputed every iteration)
//   z    = softshrink(B, th0)
//   3x:  z = softshrink(S[i] @ z + We @ x, th[i+1])
//
// CTA = 128 px x 256 dict, 512 threads (4 dict-groups x 4 px-groups),
// warp tile 64d x 32px, m16n8k8 tf32.
// z (rows 0..255) + x (rows 256..319) resident in smem, XOR-swizzled.
// Weights pre-converted to tf32 chunk layout by a prep kernel, streamed
// via cp.async through 3 smem buffers, 1 barrier per 16-k chunk.
// ------------------------------------------------------------------

#define ZROWS      320
#define ZT_WORDS   (ZROWS * 128)          // 40960
#define WSTRIDE    20                     // words per W row (16 k + pad)
#define WBUF_WORDS (256 * WSTRIDE)        // 5120
#define SMEM_BYTES ((ZT_WORDS + 3 * WBUF_WORDS) * 4)   // 225280
#define N_CHUNKS   64                     // 4 + 3*(16+4)

__device__ u32 g_wprep[52 * 4096];        // 52 unique chunks, tf32 bits

__device__ __forceinline__ u32 smem_u32(const void* p) {
    u32 a;
    asm("{ .reg .u64 t; cvta.to.shared.u64 t, %1; cvt.u32.u64 %0, t; }"
        : "=r"(a) : "l"(p));
    return a;
}
__device__ __forceinline__ u32 f2tf32(float f) {
    u32 r; asm("cvt.rna.tf32.f32 %0, %1;" : "=r"(r) : "f"(f)); return r;
}
__device__ __forceinline__ float tf(float f) { return __uint_as_float(f2tf32(f)); }
__device__ __forceinline__ float sshrink(float f, float th) {
    return f - fminf(fmaxf(f, -th), th);
}
__device__ __forceinline__ void mma8(float* c, const u32* a, u32 b0, u32 b1) {
    asm volatile(
        "mma.sync.aligned.m16n8k8.row.col.f32.tf32.tf32.f32 "
        "{%0,%1,%2,%3}, {%4,%5,%6,%7}, {%8,%9}, {%0,%1,%2,%3};"
        : "+f"(c[0]), "+f"(c[1]), "+f"(c[2]), "+f"(c[3])
        : "r"(a[0]), "r"(a[1]), "r"(a[2]), "r"(a[3]), "r"(b0), "r"(b1));
}

// execution chunk i -> (unique chunk id in g_wprep, k-row base in Zt)
__device__ __forceinline__ void chunk_info(int i, int& cid, int& kbase) {
    if (i < 4) { cid = i; kbase = 256 + i * 16; return; }
    int rme = i - 4;
    int g = rme / 20;
    int j = rme - g * 20;
    if (j < 16) { cid = 4 + g * 16 + j; kbase = j * 16; }
    else        { cid = j - 16;         kbase = 256 + (j - 16) * 16; }
}

__device__ __forceinline__ void stage_chunk(u32 wsb, int i, int tid) {
    int cid, kb; chunk_info(i, cid, kb);
    const u32* src = g_wprep + (size_t)cid * 4096;
    const u32 bufb = wsb + (u32)(i % 3) * (WBUF_WORDS * 4);
#pragma unroll
    for (int e = 0; e < 2; e++) {
        const int s    = tid + e * 512;          // 1024 x 16B segments
        const int row  = s >> 2;
        const int part = s & 3;
        const u32 dst  = bufb + (u32)(row * WSTRIDE + part * 4) * 4;
        const u32* g   = src + row * 16 + part * 4;
        asm volatile("cp.async.ca.shared.global [%0], [%1], 16;"
                     :: "r"(dst), "l"(g) : "memory");
    }
    asm volatile("cp.async.commit_group;" ::: "memory");
}

// ---------------- prep: convert We/S to tf32 chunk layout ----------------
__global__ void __launch_bounds__(1024, 2)
lista_prep(const float* __restrict__ We, const float* __restrict__ S)
{
    const int idx = blockIdx.x * 1024 + threadIdx.x;
    if (idx >= 52 * 4096) return;
    const int chunk = idx >> 12;
    const int rem   = idx & 4095;
    const int row   = rem >> 4;
    const int kk    = rem & 15;
    float v;
    if (chunk < 4) {
        v = We[row * 64 + chunk * 16 + kk];
    } else {
        const int c = chunk - 4, g = c >> 4, j = c & 15;
        v = S[g * 65536 + row * 256 + j * 16 + kk];
    }
    g_wprep[idx] = f2tf32(v);
}

// ---------------- main fused kernel ----------------
__global__ void __launch_bounds__(512, 1)
lista_main(const float* __restrict__ x,
           const float* __restrict__ th,
           float* __restrict__ out)
{
    extern __shared__ float smem[];
    float* Zt = smem;                               // [320][128], XOR-swizzled
    u32*  Wb  = reinterpret_cast<u32*>(smem + ZT_WORDS);

    const int tid  = threadIdx.x;
    const int lane = tid & 31;
    const int wid  = tid >> 5;
    const int wd   = wid & 3;                       // dict group (64 d)
    const int wp   = wid >> 2;                      // pixel group (32 px)
    const int r    = lane >> 2;
    const int c    = lane & 3;

    const int pix0 = blockIdx.x * 128;
    const int b    = pix0 >> 16;                    // 65536 px per image
    const int hw0  = pix0 & 65535;

    const u32 wsb = smem_u32(Wb);

    // kick off the cp.async pipeline immediately
    stage_chunk(wsb, 0, tid);
    stage_chunk(wsb, 1, tid);

    const float th0 = __ldg(th + 0), th1 = __ldg(th + 1);
    const float th2 = __ldg(th + 2), th3 = __ldg(th + 3);

    // ---- stage x (tf32) into rows 256..319, swizzled ----
    {
        const float* xb = x + (size_t)b * 64 * 65536 + hw0;
#pragma unroll
        for (int e = 0; e < 16; e++) {
            const int idx = tid + e * 512;          // 8192 = 64ch * 128px
            const int px  = idx & 127;
            const int ch  = idx >> 7;
            Zt[(256 + ch) * 128 + (px ^ ((ch & 3) << 3))] =
                tf(__ldg(xb + (size_t)ch * 65536 + px));
        }
    }

    float acc[4][4][4];
#pragma unroll
    for (int mt = 0; mt < 4; mt++)
#pragma unroll
        for (int nt = 0; nt < 4; nt++)
#pragma unroll
            for (int q = 0; q < 4; q++) acc[mt][nt][q] = 0.0f;

    const u32* Zu = reinterpret_cast<const u32*>(Zt);

#pragma unroll 1
    for (int i = 0; i < N_CHUNKS; i++) {
        if (i < N_CHUNKS - 1)
            asm volatile("cp.async.wait_group 1;" ::: "memory");
        else
            asm volatile("cp.async.wait_group 0;" ::: "memory");
        __syncthreads();                 // chunk i ready everywhere; prior
                                         // epilogue z-writes published;
                                         // buf (i+2)%3 free for overwrite
        if (i + 2 < N_CHUNKS) stage_chunk(wsb, i + 2, tid);

        int cid_u, kbase; chunk_info(i, cid_u, kbase);
        const u32* Wu = Wb + (i % 3) * WBUF_WORDS;

#pragma unroll
        for (int ks = 0; ks < 2; ks++) {
            u32 a[4][4];
            const int ab = (wd * 64 + r) * WSTRIDE + c + ks * 8;
#pragma unroll
            for (int mt = 0; mt < 4; mt++) {
                const u32* p = Wu + ab + mt * 16 * WSTRIDE;
                a[mt][0] = p[0];
                a[mt][1] = p[8 * WSTRIDE];
                a[mt][2] = p[4];
                a[mt][3] = p[8 * WSTRIDE + 4];
            }
            const int zb = (kbase + ks * 8 + c) * 128 + wp * 32 + r;
            u32 bf[4][2];
#pragma unroll
            for (int nt = 0; nt < 4; nt++) {
                const int o = zb + ((nt ^ c) << 3);
                bf[nt][0] = Zu[o];
                bf[nt][1] = Zu[o + 4 * 128];
            }
#pragma unroll
            for (int mt = 0; mt < 4; mt++)
#pragma unroll
                for (int nt = 0; nt < 4; nt++)
                    mma8(acc[mt][nt], a[mt], bf[nt][0], bf[nt][1]);
        }

        // iteration boundaries: write z = softshrink(acc, theta), reset acc.
        // Safe without a barrier: in-flight chunks here are We-append chunks
        // (or GEMM0), which read only x rows 256..319.
        if (i == 3 || i == 23 || i == 43) {
            const float theta = (i == 3) ? th0 : (i == 23) ? th1 : th2;
            const int key = (r & 3) << 3;
#pragma unroll
            for (int mt = 0; mt < 4; mt++) {
                const int d0 = wd * 64 + mt * 16 + r;
#pragma unroll
                for (int nt = 0; nt < 4; nt++) {
                    const int col = wp * 32 + ((nt << 3) ^ key) + 2 * c;
                    float2 v0 = make_float2(tf(sshrink(acc[mt][nt][0], theta)),
                                            tf(sshrink(acc[mt][nt][1], theta)));
                    float2 v1 = make_float2(tf(sshrink(acc[mt][nt][2], theta)),
                                            tf(sshrink(acc[mt][nt][3], theta)));
                    *reinterpret_cast<float2*>(Zt + d0 * 128 + col)       = v0;
                    *reinterpret_cast<float2*>(Zt + (d0 + 8) * 128 + col) = v1;
                    acc[mt][nt][0] = 0.0f; acc[mt][nt][1] = 0.0f;
                    acc[mt][nt][2] = 0.0f; acc[mt][nt][3] = 0.0f;
                }
            }
        }
    }

    // ---- final epilogue: out = softshrink(acc, th3) straight to gmem ----
    {
        float* ob = out + (size_t)b * 256 * 65536 + hw0;
#pragma unroll
        for (int mt = 0; mt < 4; mt++) {
            const int d0 = wd * 64 + mt * 16 + r;
#pragma unroll
            for (int nt = 0; nt < 4; nt++) {
                const int px0 = wp * 32 + nt * 8 + 2 * c;
                *reinterpret_cast<float2*>(ob + (size_t)d0 * 65536 + px0) =
                    make_float2(sshrink(acc[mt][nt][0], th3),
                                sshrink(acc[mt][nt][1], th3));
                *reinterpret_cast<float2*>(ob + (size_t)(d0 + 8) * 65536 + px0) =
                    make_float2(sshrink(acc[mt][nt][2], th3),
                                sshrink(acc[mt][nt][3], th3));
            }
        }
    }
}

extern "C" void kernel_launch(void* const* d_in, const int* in_sizes, int n_in,
                              void* d_out, int out_size)
{
    (void)in_sizes; (void)n_in; (void)out_size;
    const float* x  = (const float*)d_in[0];
    const float* We = (const float*)d_in[1];
    const float* S  = (const float*)d_in[2];
    const float* th = (const float*)d_in[3];
    float* out      = (float*)d_out;

    lista_prep<<<208, 1024>>>(We, S);

    cudaFuncSetAttribute(lista_main, cudaFuncAttributeMaxDynamicSharedMemorySize,
                         SMEM_BYTES);
    lista_main<<<2048, 512, SMEM_BYTES>>>(x, th, out);
}

// round 8
// speedup vs baseline: 2.1843x; 2.1530x over previous
#include <cuda_runtime.h>
#include <cuda_fp16.h>
#include <cstdint>

typedef uint32_t u32;

// ------------------------------------------------------------------
// LISTA fused, mma.sync f16 (m16n8k16, fp32 accum), round 8.
//   B    = We @ x            (K=64, recomputed every iteration)
//   z    = softshrink(B, th0)
//   3x:  z = softshrink(S[i] @ z + We @ x, th[i+1])
//
// CTA = 128 px x 256 dict, 256 threads = 8 warps (4 dict x 2 px),
// warp tile 64d x 64px. z + x resident in smem as k-pair-packed half2
// (XOR swizzle). Weights pre-packed to fragment order (prep kernel),
// streamed via cp.async through 3 smem buffers; 32 chunks of K=32.
// R8 fix: B-fragment smem reads go through the C++ pointer (LDS), not
// a generic deref of a cvta.to.shared address (R7's IMA).
// ------------------------------------------------------------------

#define ZP_ROWS    160                   // 128 z pair-rows + 32 x pair-rows
#define ZP_WORDS   (ZP_ROWS * 128)       // 20480 u32 (half2 each)
#define WBUF_WORDS 4096                  // one chunk: 256d x 32k fp16, frag order
#define SMEM_BYTES ((ZP_WORDS + 3 * WBUF_WORDS) * 4)   // 131072
#define N_CHUNKS   32                    // 2 + 3*(8+2)
#define N_UNIQUE   26                    // 2 We + 24 S

__device__ __align__(16) u32 g_wfrag[N_UNIQUE * WBUF_WORDS];

__device__ __forceinline__ u32 smem_u32(const void* p) {
    u32 a;
    asm("{ .reg .u64 t; cvta.to.shared.u64 t, %1; cvt.u32.u64 %0, t; }"
        : "=r"(a) : "l"(p));
    return a;
}
__device__ __forceinline__ float sshrink(float f, float th) {
    return f - fminf(fmaxf(f, -th), th);
}
__device__ __forceinline__ void mma16(float* c, const u32* a, u32 b0, u32 b1) {
    asm volatile(
        "mma.sync.aligned.m16n8k16.row.col.f32.f16.f16.f32 "
        "{%0,%1,%2,%3}, {%4,%5,%6,%7}, {%8,%9}, {%0,%1,%2,%3};"
        : "+f"(c[0]), "+f"(c[1]), "+f"(c[2]), "+f"(c[3])
        : "r"(a[0]), "r"(a[1]), "r"(a[2]), "r"(a[3]), "r"(b0), "r"(b1));
}
__device__ __forceinline__ void lds128(u32* r, u32 addr) {
    asm volatile("ld.shared.v4.b32 {%0,%1,%2,%3}, [%4];"
                 : "=r"(r[0]), "=r"(r[1]), "=r"(r[2]), "=r"(r[3]) : "r"(addr));
}

// exec chunk i -> (unique chunk id, pair-row base in Zkp)
__device__ __forceinline__ void chunk_info(int i, int& cid, int& kpb) {
    if (i < 2) { cid = i; kpb = 128 + i * 16; return; }
    const int rme = i - 2;
    const int g = rme / 10;
    const int j = rme - g * 10;
    if (j < 8) { cid = 2 + g * 8 + j; kpb = j * 16; }
    else       { cid = j - 8;         kpb = 128 + (j - 8) * 16; }
}

__device__ __forceinline__ void stage_chunk(u32 wsb, int i, int tid) {
    int cid, kpb; chunk_info(i, cid, kpb);
    const u32* src = g_wfrag + (size_t)cid * WBUF_WORDS;
    const u32 dstb = wsb + (u32)(i % 3) * (WBUF_WORDS * 4);
#pragma unroll
    for (int e = 0; e < 4; e++) {
        const int w = (tid + e * 256) * 4;           // 16B segment
        asm volatile("cp.async.ca.shared.global [%0], [%1], 16;"
                     :: "r"(dstb + (u32)w * 4), "l"(src + w) : "memory");
    }
    asm volatile("cp.async.commit_group;" ::: "memory");
}

// ------------- prep: pack We/S into fp16 a-fragment order -------------
// word layout per chunk: [wd 2][step 1][mt 2][lane 5][reg 2]
//   d = wd*64 + mt*16 + (reg&1)*8 + (lane>>2)
//   k = step*16 + (reg>>1)*8 + (lane&3)*2  (+0,+1 packed in the word)
__global__ void __launch_bounds__(256, 4)
lista_prep(const float* __restrict__ We, const float* __restrict__ S)
{
    const int w = blockIdx.x * 256 + threadIdx.x;
    if (w >= N_UNIQUE * WBUF_WORDS) return;
    const int chunk = w >> 12;
    const int rem   = w & 4095;
    const int wd    = rem >> 10;
    const int step  = (rem >> 9) & 1;
    const int mt    = (rem >> 7) & 3;
    const int lane  = (rem >> 2) & 31;
    const int reg   = rem & 3;
    const int d = wd * 64 + mt * 16 + (reg & 1) * 8 + (lane >> 2);
    const int k = step * 16 + (reg >> 1) * 8 + (lane & 3) * 2;
    float v0, v1;
    if (chunk < 2) {
        v0 = We[d * 64 + chunk * 32 + k];
        v1 = We[d * 64 + chunk * 32 + k + 1];
    } else {
        const int c = chunk - 2, g = c >> 3, j = c & 7;
        v0 = S[g * 65536 + d * 256 + j * 32 + k];
        v1 = S[g * 65536 + d * 256 + j * 32 + k + 1];
    }
    __half2 h = __floats2half2_rn(v0, v1);
    g_wfrag[w] = *reinterpret_cast<u32*>(&h);
}

// ---------------- main fused kernel ----------------
__global__ void __launch_bounds__(256, 1)
lista_main(const float* __restrict__ x,
           const float* __restrict__ th,
           float* __restrict__ out)
{
    extern __shared__ u32 smem[];
    u32* Zkp = smem;                        // [160 pair-rows][128 px] half2
    u32* Wb  = smem + ZP_WORDS;             // 3 x 4096 words

    const int tid  = threadIdx.x;
    const int lane = tid & 31;
    const int wid  = tid >> 5;
    const int wd   = wid & 3;               // dict group (64 d)
    const int wp   = wid >> 2;              // pixel group (64 px)
    const int r    = lane >> 2;
    const int c    = lane & 3;

    const int pix0 = blockIdx.x * 128;
    const int b    = pix0 >> 16;            // 65536 px per image
    const int hw0  = pix0 & 65535;

    const u32 wsb = smem_u32(Wb);

    stage_chunk(wsb, 0, tid);
    stage_chunk(wsb, 1, tid);

    const float th0 = __ldg(th + 0), th1 = __ldg(th + 1);
    const float th2 = __ldg(th + 2), th3 = __ldg(th + 3);

    // ---- stage x into pair-rows 128..159 (half2 = channels 2j, 2j+1) ----
    {
        const float* xb = x + (size_t)b * 64 * 65536 + hw0;
#pragma unroll
        for (int e = 0; e < 16; e++) {
            const int idx = tid + e * 256;          // 4096 = 32 prow * 128 px
            const int px  = idx & 127;
            const int pr  = idx >> 7;               // 0..31
            const float v0 = __ldg(xb + (size_t)(2 * pr) * 65536 + px);
            const float v1 = __ldg(xb + (size_t)(2 * pr + 1) * 65536 + px);
            __half2 h = __floats2half2_rn(v0, v1);
            Zkp[(128 + pr) * 128 + (px ^ ((pr & 3) << 3))] =
                *reinterpret_cast<u32*>(&h);
        }
    }

    float acc[4][8][4];
#pragma unroll
    for (int mt = 0; mt < 4; mt++)
#pragma unroll
        for (int nt = 0; nt < 8; nt++)
#pragma unroll
            for (int q = 0; q < 4; q++) acc[mt][nt][q] = 0.0f;

#pragma unroll 1
    for (int i = 0; i < N_CHUNKS; i++) {
        if (i < N_CHUNKS - 1)
            asm volatile("cp.async.wait_group 1;" ::: "memory");
        else
            asm volatile("cp.async.wait_group 0;" ::: "memory");
        __syncthreads();            // chunk i ready; epilogue z writes
                                    // published; buf (i+2)%3 reusable
        if (i + 2 < N_CHUNKS) stage_chunk(wsb, i + 2, tid);

        int cid, kpb; chunk_info(i, cid, kpb);
        const u32 wbuf = wsb + (u32)(i % 3) * (WBUF_WORDS * 4);

#pragma unroll
        for (int step = 0; step < 2; step++) {
            // A fragments: 4 x LDS.128 from pre-packed fragment layout
            u32 a[4][4];
#pragma unroll
            for (int mt = 0; mt < 4; mt++)
                lds128(a[mt], wbuf +
                       (u32)(((wd * 8 + step * 4 + mt) * 32 + lane) * 16));
            // B fragments: k-pair rows, XOR swizzle; n = wp*64 + nt*8 + r
            const int prow = kpb + step * 8 + c;
            const u32* zrow = Zkp + prow * 128;     // proper smem pointer (LDS)
            const int nb = wp * 64 + r;
            u32 bf[8][2];
#pragma unroll
            for (int nt = 0; nt < 8; nt++) {
                const int col = nb + (((nt ^ c) & 7) << 3);
                bf[nt][0] = zrow[col];
                bf[nt][1] = zrow[4 * 128 + col];
            }
#pragma unroll
            for (int mt = 0; mt < 4; mt++)
#pragma unroll
                for (int nt = 0; nt < 8; nt++)
                    mma16(acc[mt][nt], a[mt], bf[nt][0], bf[nt][1]);
        }

        // iteration boundaries: z = softshrink(acc, theta) -> Zkp, acc = 0.
        // Safe: in-flight prefetches are weight cp.async only; next z-reading
        // MMAs start after the next __syncthreads.
        if (i == 1 || i == 11 || i == 21) {
            const float theta = (i == 1) ? th0 : (i == 11) ? th1 : th2;
            const bool odd = (r & 1);
#pragma unroll
            for (int mt = 0; mt < 4; mt++) {
                const int prow_lo = wd * 32 + mt * 8 + (r >> 1);
                const int prow    = odd ? (prow_lo + 4) : prow_lo;
                const int swz     = (prow & 3) << 3;
#pragma unroll
                for (int nt = 0; nt < 8; nt++) {
                    const float s0 = sshrink(acc[mt][nt][0], theta);
                    const float s1 = sshrink(acc[mt][nt][1], theta);
                    const float s2 = sshrink(acc[mt][nt][2], theta);
                    const float s3 = sshrink(acc[mt][nt][3], theta);
                    const float o0 = __shfl_xor_sync(0xffffffffu, s0, 4);
                    const float o1 = __shfl_xor_sync(0xffffffffu, s1, 4);
                    const float o2 = __shfl_xor_sync(0xffffffffu, s2, 4);
                    const float o3 = __shfl_xor_sync(0xffffffffu, s3, 4);
                    __half2 h0, h1;
                    if (!odd) { h0 = __floats2half2_rn(s0, o0);
                                h1 = __floats2half2_rn(s1, o1); }
                    else      { h0 = __floats2half2_rn(o2, s2);
                                h1 = __floats2half2_rn(o3, s3); }
                    const int col = (wp * 64 + nt * 8 + 2 * c) ^ swz;
                    uint2 v;
                    v.x = *reinterpret_cast<u32*>(&h0);
                    v.y = *reinterpret_cast<u32*>(&h1);
                    *reinterpret_cast<uint2*>(Zkp + prow * 128 + col) = v;
                    acc[mt][nt][0] = 0.0f; acc[mt][nt][1] = 0.0f;
                    acc[mt][nt][2] = 0.0f; acc[mt][nt][3] = 0.0f;
                }
            }
        }
    }

    // ---- final epilogue: out = softshrink(acc, th3) -> gmem ----
    {
        float* ob = out + (size_t)b * 256 * 65536 + hw0;
#pragma unroll
        for (int mt = 0; mt < 4; mt++) {
            const int d0 = wd * 64 + mt * 16 + r;
#pragma unroll
            for (int nt = 0; nt < 8; nt++) {
                const int px0 = wp * 64 + nt * 8 + 2 * c;
                *reinterpret_cast<float2*>(ob + (size_t)d0 * 65536 + px0) =
                    make_float2(sshrink(acc[mt][nt][0], th3),
                                sshrink(acc[mt][nt][1], th3));
                *reinterpret_cast<float2*>(ob + (size_t)(d0 + 8) * 65536 + px0) =
                    make_float2(sshrink(acc[mt][nt][2], th3),
                                sshrink(acc[mt][nt][3], th3));
            }
        }
    }
}

extern "C" void kernel_launch(void* const* d_in, const int* in_sizes, int n_in,
                              void* d_out, int out_size)
{
    (void)in_sizes; (void)n_in; (void)out_size;
    const float* x  = (const float*)d_in[0];
    const float* We = (const float*)d_in[1];
    const float* S  = (const float*)d_in[2];
    const float* th = (const float*)d_in[3];
    float* out      = (float*)d_out;

    lista_prep<<<(N_UNIQUE * WBUF_WORDS + 255) / 256, 256>>>(We, S);

    cudaFuncSetAttribute(lista_main, cudaFuncAttributeMaxDynamicSharedMemorySize,
                         SMEM_BYTES);
    lista_main<<<2048, 256, SMEM_BYTES>>>(x, th, out);
}

// round 9
// speedup vs baseline: 2.4660x; 1.1290x over previous
#include <cuda_runtime.h>
#include <cuda_fp16.h>
#include <cstdint>

typedef uint32_t u32;

// ------------------------------------------------------------------
// LISTA fused, mma.sync f16 (m16n8k16, fp32 accum), round 9.
//   B    = We @ x            (K=64, recomputed every iteration)
//   z    = softshrink(B, th0)
//   3x:  z = softshrink(S[i] @ z + We @ x, th[i+1])
//
// CTA = 128 px x 256 dict, 512 threads = 16 warps (4 dict x 4 px),
// warp tile 64d x 32px (acc = 64 regs -> no RF pressure, 4 warps/SMSP).
// z + x resident in smem as k-pair-packed half2 (XOR swizzle).
// Weights pre-packed to fragment order, streamed via cp.async through
// 3 smem buffers; 16 chunks of K=64 (one barrier per chunk).
// ------------------------------------------------------------------

#define ZP_ROWS    160                   // 128 z pair-rows + 32 x pair-rows
#define ZP_WORDS   (ZP_ROWS * 128)       // 20480 u32 (half2 each)
#define WBUF_WORDS 8192                  // one chunk: 256d x 64k fp16, frag order
#define SMEM_BYTES ((ZP_WORDS + 3 * WBUF_WORDS) * 4)   // 180224
#define N_CHUNKS   16                    // 1 We + 3*(4 S + 1 We)
#define N_UNIQUE   13                    // 1 We + 12 S

__device__ __align__(16) u32 g_wfrag[N_UNIQUE * WBUF_WORDS];

__device__ __forceinline__ u32 smem_u32(const void* p) {
    u32 a;
    asm("{ .reg .u64 t; cvta.to.shared.u64 t, %1; cvt.u32.u64 %0, t; }"
        : "=r"(a) : "l"(p));
    return a;
}
__device__ __forceinline__ float sshrink(float f, float th) {
    return f - fminf(fmaxf(f, -th), th);
}
__device__ __forceinline__ void mma16(float* c, const u32* a, u32 b0, u32 b1) {
    asm volatile(
        "mma.sync.aligned.m16n8k16.row.col.f32.f16.f16.f32 "
        "{%0,%1,%2,%3}, {%4,%5,%6,%7}, {%8,%9}, {%0,%1,%2,%3};"
        : "+f"(c[0]), "+f"(c[1]), "+f"(c[2]), "+f"(c[3])
        : "r"(a[0]), "r"(a[1]), "r"(a[2]), "r"(a[3]), "r"(b0), "r"(b1));
}
__device__ __forceinline__ void lds128(u32* r, u32 addr) {
    asm volatile("ld.shared.v4.b32 {%0,%1,%2,%3}, [%4];"
                 : "=r"(r[0]), "=r"(r[1]), "=r"(r[2]), "=r"(r[3]) : "r"(addr));
}

// exec chunk i -> (unique chunk id, pair-row base in Zkp)
// i=0: We (x rows). Then groups of 5: 4 S chunks + 1 We-append.
__device__ __forceinline__ void chunk_info(int i, int& cid, int& kpb) {
    if (i == 0) { cid = 0; kpb = 128; return; }
    const int rme = i - 1;
    const int g = rme / 5;
    const int j = rme - g * 5;
    if (j < 4) { cid = 1 + g * 4 + j; kpb = j * 32; }
    else       { cid = 0;             kpb = 128; }
}

__device__ __forceinline__ void stage_chunk(u32 wsb, int i, int tid) {
    int cid, kpb; chunk_info(i, cid, kpb);
    const u32* src = g_wfrag + (size_t)cid * WBUF_WORDS;
    const u32 dstb = wsb + (u32)(i % 3) * (WBUF_WORDS * 4);
#pragma unroll
    for (int e = 0; e < 4; e++) {
        const int w = (tid + e * 512) * 4;           // 16B segment
        asm volatile("cp.async.ca.shared.global [%0], [%1], 16;"
                     :: "r"(dstb + (u32)w * 4), "l"(src + w) : "memory");
    }
    asm volatile("cp.async.commit_group;" ::: "memory");
}

// ------------- prep: pack We/S into fp16 a-fragment order -------------
// word layout per chunk: [wd 2][step 2][mt 2][lane 5][reg 2]  (8192 words)
//   d = wd*64 + mt*16 + (reg&1)*8 + (lane>>2)
//   k = step*16 + (reg>>1)*8 + (lane&3)*2  (+0,+1 packed in the word)
__global__ void __launch_bounds__(256, 4)
lista_prep(const float* __restrict__ We, const float* __restrict__ S)
{
    const int w = blockIdx.x * 256 + threadIdx.x;
    if (w >= N_UNIQUE * WBUF_WORDS) return;
    const int chunk = w >> 13;
    const int rem   = w & 8191;
    const int wd    = rem >> 11;
    const int step  = (rem >> 9) & 3;
    const int mt    = (rem >> 7) & 3;
    const int lane  = (rem >> 2) & 31;
    const int reg   = rem & 3;
    const int d = wd * 64 + mt * 16 + (reg & 1) * 8 + (lane >> 2);
    const int k = step * 16 + (reg >> 1) * 8 + (lane & 3) * 2;
    float v0, v1;
    if (chunk == 0) {
        v0 = We[d * 64 + k];
        v1 = We[d * 64 + k + 1];
    } else {
        const int c = chunk - 1, g = c >> 2, j = c & 3;
        v0 = S[g * 65536 + d * 256 + j * 64 + k];
        v1 = S[g * 65536 + d * 256 + j * 64 + k + 1];
    }
    __half2 h = __floats2half2_rn(v0, v1);
    g_wfrag[w] = *reinterpret_cast<u32*>(&h);
}

// ---------------- main fused kernel ----------------
__global__ void __launch_bounds__(512, 1)
lista_main(const float* __restrict__ x,
           const float* __restrict__ th,
           float* __restrict__ out)
{
    extern __shared__ u32 smem[];
    u32* Zkp = smem;                        // [160 pair-rows][128 px] half2
    u32* Wb  = smem + ZP_WORDS;             // 3 x 8192 words

    const int tid  = threadIdx.x;
    const int lane = tid & 31;
    const int wid  = tid >> 5;
    const int wd   = wid & 3;               // dict group (64 d)
    const int wp   = wid >> 2;              // pixel group (32 px)
    const int r    = lane >> 2;
    const int c    = lane & 3;

    const int pix0 = blockIdx.x * 128;
    const int b    = pix0 >> 16;            // 65536 px per image
    const int hw0  = pix0 & 65535;

    const u32 wsb = smem_u32(Wb);

    stage_chunk(wsb, 0, tid);
    stage_chunk(wsb, 1, tid);

    const float th0 = __ldg(th + 0), th1 = __ldg(th + 1);
    const float th2 = __ldg(th + 2), th3 = __ldg(th + 3);

    // ---- stage x into pair-rows 128..159 (half2 = channels 2j, 2j+1) ----
    {
        const float* xb = x + (size_t)b * 64 * 65536 + hw0;
#pragma unroll
        for (int e = 0; e < 8; e++) {
            const int idx = tid + e * 512;          // 4096 = 32 prow * 128 px
            const int px  = idx & 127;
            const int pr  = idx >> 7;               // 0..31
            const float v0 = __ldg(xb + (size_t)(2 * pr) * 65536 + px);
            const float v1 = __ldg(xb + (size_t)(2 * pr + 1) * 65536 + px);
            __half2 h = __floats2half2_rn(v0, v1);
            Zkp[(128 + pr) * 128 + (px ^ ((pr & 3) << 3))] =
                *reinterpret_cast<u32*>(&h);
        }
    }

    float acc[4][4][4];
#pragma unroll
    for (int mt = 0; mt < 4; mt++)
#pragma unroll
        for (int nt = 0; nt < 4; nt++)
#pragma unroll
            for (int q = 0; q < 4; q++) acc[mt][nt][q] = 0.0f;

#pragma unroll 1
    for (int i = 0; i < N_CHUNKS; i++) {
        if (i < N_CHUNKS - 1)
            asm volatile("cp.async.wait_group 1;" ::: "memory");
        else
            asm volatile("cp.async.wait_group 0;" ::: "memory");
        __syncthreads();            // chunk i ready; epilogue z writes
                                    // published; buf (i+2)%3 reusable
        if (i + 2 < N_CHUNKS) stage_chunk(wsb, i + 2, tid);

        int cid, kpb; chunk_info(i, cid, kpb);
        const u32 wbuf = wsb + (u32)(i % 3) * (WBUF_WORDS * 4);

#pragma unroll
        for (int step = 0; step < 4; step++) {
            // A fragments: 4 x LDS.128 from pre-packed fragment layout
            u32 a[4][4];
#pragma unroll
            for (int mt = 0; mt < 4; mt++)
                lds128(a[mt], wbuf +
                       (u32)(((wd * 16 + step * 4 + mt) * 32 + lane) * 16));
            // B fragments: pair-rows kpb+step*8+c (and +4), XOR swizzle
            const int prow = kpb + step * 8 + c;
            const u32* zrow = Zkp + prow * 128;
            const int nb = wp * 32 + r;
            u32 bf[4][2];
#pragma unroll
            for (int nt = 0; nt < 4; nt++) {
                const int col = nb + (((nt ^ c) & 3) << 3);
                bf[nt][0] = zrow[col];
                bf[nt][1] = zrow[4 * 128 + col];
            }
#pragma unroll
            for (int mt = 0; mt < 4; mt++)
#pragma unroll
                for (int nt = 0; nt < 4; nt++)
                    mma16(acc[mt][nt], a[mt], bf[nt][0], bf[nt][1]);
        }

        // iteration boundaries: z = softshrink(acc, theta) -> Zkp, acc = 0.
        // Safe: next z-reading MMAs start after the next __syncthreads.
        if (i == 0 || i == 5 || i == 10) {
            const float theta = (i == 0) ? th0 : (i == 5) ? th1 : th2;
            const bool odd = (r & 1);
#pragma unroll
            for (int mt = 0; mt < 4; mt++) {
                const int prow_lo = wd * 32 + mt * 8 + (r >> 1);
                const int prow    = odd ? (prow_lo + 4) : prow_lo;
                const int swz     = (prow & 3) << 3;
#pragma unroll
                for (int nt = 0; nt < 4; nt++) {
                    const float s0 = sshrink(acc[mt][nt][0], theta);
                    const float s1 = sshrink(acc[mt][nt][1], theta);
                    const float s2 = sshrink(acc[mt][nt][2], theta);
                    const float s3 = sshrink(acc[mt][nt][3], theta);
                    const float o0 = __shfl_xor_sync(0xffffffffu, s0, 4);
                    const float o1 = __shfl_xor_sync(0xffffffffu, s1, 4);
                    const float o2 = __shfl_xor_sync(0xffffffffu, s2, 4);
                    const float o3 = __shfl_xor_sync(0xffffffffu, s3, 4);
                    __half2 h0, h1;
                    if (!odd) { h0 = __floats2half2_rn(s0, o0);
                                h1 = __floats2half2_rn(s1, o1); }
                    else      { h0 = __floats2half2_rn(o2, s2);
                                h1 = __floats2half2_rn(o3, s3); }
                    const int col = (wp * 32 + nt * 8 + 2 * c) ^ swz;
                    uint2 v;
                    v.x = *reinterpret_cast<u32*>(&h0);
                    v.y = *reinterpret_cast<u32*>(&h1);
                    *reinterpret_cast<uint2*>(Zkp + prow * 128 + col) = v;
                    acc[mt][nt][0] = 0.0f; acc[mt][nt][1] = 0.0f;
                    acc[mt][nt][2] = 0.0f; acc[mt][nt][3] = 0.0f;
                }
            }
        }
    }

    // ---- final epilogue: out = softshrink(acc, th3) -> gmem ----
    {
        float* ob = out + (size_t)b * 256 * 65536 + hw0;
#pragma unroll
        for (int mt = 0; mt < 4; mt++) {
            const int d0 = wd * 64 + mt * 16 + r;
#pragma unroll
            for (int nt = 0; nt < 4; nt++) {
                const int px0 = wp * 32 + nt * 8 + 2 * c;
                *reinterpret_cast<float2*>(ob + (size_t)d0 * 65536 + px0) =
                    make_float2(sshrink(acc[mt][nt][0], th3),
                                sshrink(acc[mt][nt][1], th3));
                *reinterpret_cast<float2*>(ob + (size_t)(d0 + 8) * 65536 + px0) =
                    make_float2(sshrink(acc[mt][nt][2], th3),
                                sshrink(acc[mt][nt][3], th3));
            }
        }
    }
}

extern "C" void kernel_launch(void* const* d_in, const int* in_sizes, int n_in,
                              void* d_out, int out_size)
{
    (void)in_sizes; (void)n_in; (void)out_size;
    const float* x  = (const float*)d_in[0];
    const float* We = (const float*)d_in[1];
    const float* S  = (const float*)d_in[2];
    const float* th = (const float*)d_in[3];
    float* out      = (float*)d_out;

    lista_prep<<<(N_UNIQUE * WBUF_WORDS + 255) / 256, 256>>>(We, S);

    cudaFuncSetAttribute(lista_main, cudaFuncAttributeMaxDynamicSharedMemorySize,
                         SMEM_BYTES);
    lista_main<<<2048, 512, SMEM_BYTES>>>(x, th, out);
}

// round 10
// speedup vs baseline: 2.5710x; 1.0426x over previous
#include <cuda_runtime.h>
#include <cuda_fp16.h>
#include <cstdint>

typedef uint32_t u32;

// ------------------------------------------------------------------
// LISTA fused, mma.sync f16 (m16n8k16, fp32 accum), round 10.
//   B    = We @ x        (computed ONCE, stored fp16 in smem)
//   z    = softshrink(B, th0)
//   3x:  z = softshrink(S[i] @ z + B, th[i+1])
//
// CTA = 128 px x 256 dict, 512 threads = 16 warps (4 dict x 4 px),
// warp tile 64d x 32px. z resident in smem (k-pair half2, XOR swizzle).
// We loaded once to smem (fragment order); after GEMM0 its region is
// re-used to hold B in per-thread accumulator order (conflict-free).
// S weights stream through 3 cp.async buffers; 12 chunks of K=64.
// ------------------------------------------------------------------

// smem word map (u32 words):
//   [0,      16384)  z: 128 pair-rows x 128 px (half2)
//   [16384,  32768)  region R: setup = x (4096 w) + We frags (8192 w @20480)
//                    after GEMM0 = B, 32 words x 512 threads (16384 w)
//   [32768,  57344)  3 x 8192-word S chunk buffers
#define Z_WORDS    16384
#define R_OFF      16384
#define WE_OFF     20480
#define BS_OFF     16384
#define SBUF_OFF   32768
#define WBUF_WORDS 8192
#define SMEM_BYTES (57344 * 4)           // 229376
#define N_SCHUNKS  12
#define N_UNIQUE   13                    // 1 We + 12 S

__device__ __align__(16) u32 g_wfrag[N_UNIQUE * WBUF_WORDS];

__device__ __forceinline__ u32 smem_u32(const void* p) {
    u32 a;
    asm("{ .reg .u64 t; cvta.to.shared.u64 t, %1; cvt.u32.u64 %0, t; }"
        : "=r"(a) : "l"(p));
    return a;
}
__device__ __forceinline__ float sshrink(float f, float th) {
    return f - fminf(fmaxf(f, -th), th);
}
__device__ __forceinline__ void mma16(float* c, const u32* a, u32 b0, u32 b1) {
    asm volatile(
        "mma.sync.aligned.m16n8k16.row.col.f32.f16.f16.f32 "
        "{%0,%1,%2,%3}, {%4,%5,%6,%7}, {%8,%9}, {%0,%1,%2,%3};"
        : "+f"(c[0]), "+f"(c[1]), "+f"(c[2]), "+f"(c[3])
        : "r"(a[0]), "r"(a[1]), "r"(a[2]), "r"(a[3]), "r"(b0), "r"(b1));
}
__device__ __forceinline__ void lds128(u32* r, u32 addr) {
    asm volatile("ld.shared.v4.b32 {%0,%1,%2,%3}, [%4];"
                 : "=r"(r[0]), "=r"(r[1]), "=r"(r[2]), "=r"(r[3]) : "r"(addr));
}

// copy one 8192-word fragment chunk gmem -> smem via cp.async, one commit
__device__ __forceinline__ void stage_words(u32 dst_sm, const u32* src, int tid) {
#pragma unroll
    for (int e = 0; e < 4; e++) {
        const int w = (tid + e * 512) * 4;           // 16B segment
        asm volatile("cp.async.ca.shared.global [%0], [%1], 16;"
                     :: "r"(dst_sm + (u32)w * 4), "l"(src + w) : "memory");
    }
    asm volatile("cp.async.commit_group;" ::: "memory");
}

// ------------- prep: pack We/S into fp16 a-fragment order -------------
// word layout per chunk: [wd 2][step 2][mt 2][lane 5][reg 2]  (8192 words)
//   d = wd*64 + mt*16 + (reg&1)*8 + (lane>>2)
//   k = step*16 + (reg>>1)*8 + (lane&3)*2  (+0,+1 packed in the word)
__global__ void __launch_bounds__(256, 4)
lista_prep(const float* __restrict__ We, const float* __restrict__ S)
{
    const int w = blockIdx.x * 256 + threadIdx.x;
    if (w >= N_UNIQUE * WBUF_WORDS) return;
    const int chunk = w >> 13;
    const int rem   = w & 8191;
    const int wd    = rem >> 11;
    const int step  = (rem >> 9) & 3;
    const int mt    = (rem >> 7) & 3;
    const int lane  = (rem >> 2) & 31;
    const int reg   = rem & 3;
    const int d = wd * 64 + mt * 16 + (reg & 1) * 8 + (lane >> 2);
    const int k = step * 16 + (reg >> 1) * 8 + (lane & 3) * 2;
    float v0, v1;
    if (chunk == 0) {
        v0 = We[d * 64 + k];
        v1 = We[d * 64 + k + 1];
    } else {
        const int c = chunk - 1, g = c >> 2, j = c & 3;
        v0 = S[g * 65536 + d * 256 + j * 64 + k];
        v1 = S[g * 65536 + d * 256 + j * 64 + k + 1];
    }
    __half2 h = __floats2half2_rn(v0, v1);
    g_wfrag[w] = *reinterpret_cast<u32*>(&h);
}

// one K=64 chunk of MMAs: acc += W(frag @ wbuf) @ z(pair-rows kpb..)
__device__ __forceinline__ void do_chunk(u32 wbuf, int kpb, const u32* Zkp,
                                         float acc[4][4][4],
                                         int wd, int wp, int lane, int r, int c)
{
#pragma unroll
    for (int step = 0; step < 4; step++) {
        u32 a[4][4];
#pragma unroll
        for (int mt = 0; mt < 4; mt++)
            lds128(a[mt], wbuf +
                   (u32)(((wd * 16 + step * 4 + mt) * 32 + lane) * 16));
        const int prow = kpb + step * 8 + c;
        const u32* zrow = Zkp + prow * 128;
        const int nb = wp * 32 + r;
        u32 bf[4][2];
#pragma unroll
        for (int nt = 0; nt < 4; nt++) {
            const int col = nb + (((nt ^ c) & 3) << 3);
            bf[nt][0] = zrow[col];
            bf[nt][1] = zrow[4 * 128 + col];
        }
#pragma unroll
        for (int mt = 0; mt < 4; mt++)
#pragma unroll
            for (int nt = 0; nt < 4; nt++)
                mma16(acc[mt][nt], a[mt], bf[nt][0], bf[nt][1]);
    }
}

// ---------------- main fused kernel ----------------
__global__ void __launch_bounds__(512, 1)
lista_main(const float* __restrict__ x,
           const float* __restrict__ th,
           float* __restrict__ out)
{
    extern __shared__ u32 smem[];
    u32* Zkp = smem;

    const int tid  = threadIdx.x;
    const int lane = tid & 31;
    const int wid  = tid >> 5;
    const int wd   = wid & 3;               // dict group (64 d)
    const int wp   = wid >> 2;              // pixel group (32 px)
    const int r    = lane >> 2;
    const int c    = lane & 3;

    const int pix0 = blockIdx.x * 128;
    const int b    = pix0 >> 16;            // 65536 px per image
    const int hw0  = pix0 & 65535;

    const u32 smb = smem_u32(smem);

    // kick off weight traffic: We (group 0), S0 (group 1), S1 (group 2)
    stage_words(smb + WE_OFF * 4, g_wfrag, tid);
    stage_words(smb + SBUF_OFF * 4, g_wfrag + WBUF_WORDS, tid);
    stage_words(smb + (SBUF_OFF + WBUF_WORDS) * 4, g_wfrag + 2 * WBUF_WORDS, tid);

    const float th0 = __ldg(th + 0), th1 = __ldg(th + 1);
    const float th2 = __ldg(th + 2), th3 = __ldg(th + 3);

    // ---- stage x into pair-rows 128..159 (words R_OFF..) ----
    {
        const float* xb = x + (size_t)b * 64 * 65536 + hw0;
#pragma unroll
        for (int e = 0; e < 8; e++) {
            const int idx = tid + e * 512;          // 4096 = 32 prow * 128 px
            const int px  = idx & 127;
            const int pr  = idx >> 7;               // 0..31
            const float v0 = __ldg(xb + (size_t)(2 * pr) * 65536 + px);
            const float v1 = __ldg(xb + (size_t)(2 * pr + 1) * 65536 + px);
            __half2 h = __floats2half2_rn(v0, v1);
            Zkp[R_OFF + pr * 128 + (px ^ ((pr & 3) << 3))] =
                *reinterpret_cast<u32*>(&h);
        }
    }

    float acc[4][4][4];
#pragma unroll
    for (int mt = 0; mt < 4; mt++)
#pragma unroll
        for (int nt = 0; nt < 4; nt++)
#pragma unroll
            for (int q = 0; q < 4; q++) acc[mt][nt][q] = 0.0f;

    // ---- GEMM0: B = We @ x (We frags resident, x pair-rows at 128) ----
    asm volatile("cp.async.wait_group 2;" ::: "memory");   // We landed
    __syncthreads();                                       // x visible too
    do_chunk(smb + WE_OFF * 4, 128, Zkp, acc, wd, wp, lane, r, c);
    __syncthreads();                 // all We/x reads done; R region reusable

    // ---- epilogue 0: B -> smem (fp16, per-thread order), z0 -> Zkp ----
    {
        const bool odd = (r & 1);
#pragma unroll
        for (int mt = 0; mt < 4; mt++) {
            const int prow_lo = wd * 32 + mt * 8 + (r >> 1);
            const int prow    = odd ? (prow_lo + 4) : prow_lo;
            const int swz     = (prow & 3) << 3;
#pragma unroll
            for (int nt = 0; nt < 4; nt++) {
                // store B (fp32 acc rounded to fp16)
                __half2 hb0 = __floats2half2_rn(acc[mt][nt][0], acc[mt][nt][1]);
                __half2 hb1 = __floats2half2_rn(acc[mt][nt][2], acc[mt][nt][3]);
                const int wB = (mt * 4 + nt) * 2;
                Zkp[BS_OFF + wB * 512 + tid]       = *reinterpret_cast<u32*>(&hb0);
                Zkp[BS_OFF + (wB + 1) * 512 + tid] = *reinterpret_cast<u32*>(&hb1);
                // z0 = softshrink(B, th0)
                const float s0 = sshrink(acc[mt][nt][0], th0);
                const float s1 = sshrink(acc[mt][nt][1], th0);
                const float s2 = sshrink(acc[mt][nt][2], th0);
                const float s3 = sshrink(acc[mt][nt][3], th0);
                const float o0 = __shfl_xor_sync(0xffffffffu, s0, 4);
                const float o1 = __shfl_xor_sync(0xffffffffu, s1, 4);
                const float o2 = __shfl_xor_sync(0xffffffffu, s2, 4);
                const float o3 = __shfl_xor_sync(0xffffffffu, s3, 4);
                __half2 h0, h1;
                if (!odd) { h0 = __floats2half2_rn(s0, o0);
                            h1 = __floats2half2_rn(s1, o1); }
                else      { h0 = __floats2half2_rn(o2, s2);
                            h1 = __floats2half2_rn(o3, s3); }
                const int col = (wp * 32 + nt * 8 + 2 * c) ^ swz;
                uint2 v;
                v.x = *reinterpret_cast<u32*>(&h0);
                v.y = *reinterpret_cast<u32*>(&h1);
                *reinterpret_cast<uint2*>(Zkp + prow * 128 + col) = v;
                acc[mt][nt][0] = 0.0f; acc[mt][nt][1] = 0.0f;
                acc[mt][nt][2] = 0.0f; acc[mt][nt][3] = 0.0f;
            }
        }
    }

    // ---- 12 S chunks (3 iterations x K=256) ----
#pragma unroll 1
    for (int i = 0; i < N_SCHUNKS; i++) {
        if (i < N_SCHUNKS - 1)
            asm volatile("cp.async.wait_group 1;" ::: "memory");
        else
            asm volatile("cp.async.wait_group 0;" ::: "memory");
        __syncthreads();         // chunk i ready; epilogue z writes published;
                                 // buf (i+2)%3 reusable
        if (i + 2 < N_SCHUNKS)
            stage_words(smb + (SBUF_OFF + ((i + 2) % 3) * WBUF_WORDS) * 4,
                        g_wfrag + (size_t)(i + 3) * WBUF_WORDS, tid);

        do_chunk(smb + (SBUF_OFF + (i % 3) * WBUF_WORDS) * 4,
                 (i & 3) * 32, Zkp, acc, wd, wp, lane, r, c);

        // iteration boundary: z = softshrink(acc + B, theta), reset acc
        if (i == 3 || i == 7) {
            const float theta = (i == 3) ? th1 : th2;
            const bool odd = (r & 1);
#pragma unroll
            for (int mt = 0; mt < 4; mt++) {
                const int prow_lo = wd * 32 + mt * 8 + (r >> 1);
                const int prow    = odd ? (prow_lo + 4) : prow_lo;
                const int swz     = (prow & 3) << 3;
#pragma unroll
                for (int nt = 0; nt < 4; nt++) {
                    const int wB = (mt * 4 + nt) * 2;
                    const u32 bw0 = Zkp[BS_OFF + wB * 512 + tid];
                    const u32 bw1 = Zkp[BS_OFF + (wB + 1) * 512 + tid];
                    const float2 b0 =
                        __half22float2(*reinterpret_cast<const __half2*>(&bw0));
                    const float2 b1 =
                        __half22float2(*reinterpret_cast<const __half2*>(&bw1));
                    const float s0 = sshrink(acc[mt][nt][0] + b0.x, theta);
                    const float s1 = sshrink(acc[mt][nt][1] + b0.y, theta);
                    const float s2 = sshrink(acc[mt][nt][2] + b1.x, theta);
                    const float s3 = sshrink(acc[mt][nt][3] + b1.y, theta);
                    const float o0 = __shfl_xor_sync(0xffffffffu, s0, 4);
                    const float o1 = __shfl_xor_sync(0xffffffffu, s1, 4);
                    const float o2 = __shfl_xor_sync(0xffffffffu, s2, 4);
                    const float o3 = __shfl_xor_sync(0xffffffffu, s3, 4);
                    __half2 h0, h1;
                    if (!odd) { h0 = __floats2half2_rn(s0, o0);
                                h1 = __floats2half2_rn(s1, o1); }
                    else      { h0 = __floats2half2_rn(o2, s2);
                                h1 = __floats2half2_rn(o3, s3); }
                    const int col = (wp * 32 + nt * 8 + 2 * c) ^ swz;
                    uint2 v;
                    v.x = *reinterpret_cast<u32*>(&h0);
                    v.y = *reinterpret_cast<u32*>(&h1);
                    *reinterpret_cast<uint2*>(Zkp + prow * 128 + col) = v;
                    acc[mt][nt][0] = 0.0f; acc[mt][nt][1] = 0.0f;
                    acc[mt][nt][2] = 0.0f; acc[mt][nt][3] = 0.0f;
                }
            }
        }
    }

    // ---- final epilogue: out = softshrink(acc + B, th3) -> gmem ----
    {
        float* ob = out + (size_t)b * 256 * 65536 + hw0;
#pragma unroll
        for (int mt = 0; mt < 4; mt++) {
            const int d0 = wd * 64 + mt * 16 + r;
#pragma unroll
            for (int nt = 0; nt < 4; nt++) {
                const int wB = (mt * 4 + nt) * 2;
                const u32 bw0 = Zkp[BS_OFF + wB * 512 + tid];
                const u32 bw1 = Zkp[BS_OFF + (wB + 1) * 512 + tid];
                const float2 b0 =
                    __half22float2(*reinterpret_cast<const __half2*>(&bw0));
                const float2 b1 =
                    __half22float2(*reinterpret_cast<const __half2*>(&bw1));
                const int px0 = wp * 32 + nt * 8 + 2 * c;
                *reinterpret_cast<float2*>(ob + (size_t)d0 * 65536 + px0) =
                    make_float2(sshrink(acc[mt][nt][0] + b0.x, th3),
                                sshrink(acc[mt][nt][1] + b0.y, th3));
                *reinterpret_cast<float2*>(ob + (size_t)(d0 + 8) * 65536 + px0) =
                    make_float2(sshrink(acc[mt][nt][2] + b1.x, th3),
                                sshrink(acc[mt][nt][3] + b1.y, th3));
            }
        }
    }
}

extern "C" void kernel_launch(void* const* d_in, const int* in_sizes, int n_in,
                              void* d_out, int out_size)
{
    (void)in_sizes; (void)n_in; (void)out_size;
    const float* x  = (const float*)d_in[0];
    const float* We = (const float*)d_in[1];
    const float* S  = (const float*)d_in[2];
    const float* th = (const float*)d_in[3];
    float* out      = (float*)d_out;

    lista_prep<<<(N_UNIQUE * WBUF_WORDS + 255) / 256, 256>>>(We, S);

    cudaFuncSetAttribute(lista_main, cudaFuncAttributeMaxDynamicSharedMemorySize,
                         SMEM_BYTES);
    lista_main<<<2048, 512, SMEM_BYTES>>>(x, th, out);
}

// round 11
// speedup vs baseline: 2.6740x; 1.0400x over previous
#include <cuda_runtime.h>
#include <cuda_fp16.h>
#include <cstdint>

typedef uint32_t u32;

// ------------------------------------------------------------------
// LISTA fused, mma.sync f16 (m16n8k16, fp32 accum), round 11.
//   B    = We @ x        (computed once, stored fp16 in smem)
//   z    = softshrink(B, th0)
//   3x:  z = softshrink(S[i] @ z + B, th[i+1])
//
// CTA = 64 px x 256 dict, 256 threads = 8 warps (4 dict x 2 px),
// warp tile 64d x 32px. TWO CTAs per SM (112 KB smem each) so one
// CTA's MMA phase overlaps the other's load/barrier phase.
// z resident in smem (k-pair half2, XOR swizzle). B in smem fp16,
// per-thread accumulator order. Weights pre-packed to fragment order,
// streamed via cp.async through 3 buffers; 26 chunks of K=32.
// ------------------------------------------------------------------

// smem u32-word map:
//   [0,     8192)  z: 128 pair-rows x 64 px (half2)
//   [8192, 16384)  setup: x (32 pair-rows x 64) ; after GEMM0: B (fp16)
//   [16384,28672)  3 x 4096-word weight chunk buffers
#define BS_OFF     8192
#define SBUF_OFF   16384
#define WBUF_WORDS 4096
#define SMEM_BYTES (28672 * 4)           // 114688
#define N_CHUNKS   26                    // 2 We + 24 S, each K=32

__device__ __align__(16) u32 g_wfrag[N_CHUNKS * WBUF_WORDS];

__device__ __forceinline__ u32 smem_u32(const void* p) {
    u32 a;
    asm("{ .reg .u64 t; cvta.to.shared.u64 t, %1; cvt.u32.u64 %0, t; }"
        : "=r"(a) : "l"(p));
    return a;
}
__device__ __forceinline__ float sshrink(float f, float th) {
    return f - fminf(fmaxf(f, -th), th);
}
__device__ __forceinline__ void mma16(float* c, const u32* a, u32 b0, u32 b1) {
    asm volatile(
        "mma.sync.aligned.m16n8k16.row.col.f32.f16.f16.f32 "
        "{%0,%1,%2,%3}, {%4,%5,%6,%7}, {%8,%9}, {%0,%1,%2,%3};"
        : "+f"(c[0]), "+f"(c[1]), "+f"(c[2]), "+f"(c[3])
        : "r"(a[0]), "r"(a[1]), "r"(a[2]), "r"(a[3]), "r"(b0), "r"(b1));
}
__device__ __forceinline__ void lds128(u32* r, u32 addr) {
    asm volatile("ld.shared.v4.b32 {%0,%1,%2,%3}, [%4];"
                 : "=r"(r[0]), "=r"(r[1]), "=r"(r[2]), "=r"(r[3]) : "r"(addr));
}

// stage one 4096-word chunk gmem -> smem, one cp.async commit group
__device__ __forceinline__ void stage_chunk(u32 dst_sm, const u32* src, int tid) {
#pragma unroll
    for (int e = 0; e < 4; e++) {
        const int w = (tid + e * 256) * 4;           // 16B segment
        asm volatile("cp.async.ca.shared.global [%0], [%1], 16;"
                     :: "r"(dst_sm + (u32)w * 4), "l"(src + w) : "memory");
    }
    asm volatile("cp.async.commit_group;" ::: "memory");
}

// ------------- prep: pack We/S into fp16 a-fragment order -------------
// word layout per K=32 chunk (4096 words): [wd 2][step 1][mt 2][lane 5][reg 2]
//   d = wd*64 + mt*16 + (reg&1)*8 + (lane>>2)
//   k = step*16 + (reg>>1)*8 + (lane&3)*2  (+0,+1 packed)
// chunk order = execution order: 0,1 = We k[0:32),k[32:64); 2.. = S.
__global__ void __launch_bounds__(256, 4)
lista_prep(const float* __restrict__ We, const float* __restrict__ S)
{
    const int w = blockIdx.x * 256 + threadIdx.x;
    if (w >= N_CHUNKS * WBUF_WORDS) return;
    const int chunk = w >> 12;
    const int rem   = w & 4095;
    const int wd    = rem >> 10;
    const int step  = (rem >> 9) & 1;
    const int mt    = (rem >> 7) & 3;
    const int lane  = (rem >> 2) & 31;
    const int reg   = rem & 3;
    const int d = wd * 64 + mt * 16 + (reg & 1) * 8 + (lane >> 2);
    const int k = step * 16 + (reg >> 1) * 8 + (lane & 3) * 2;
    float v0, v1;
    if (chunk < 2) {
        v0 = We[d * 64 + chunk * 32 + k];
        v1 = We[d * 64 + chunk * 32 + k + 1];
    } else {
        const int c = chunk - 2, g = c >> 3, j = c & 7;
        v0 = S[g * 65536 + d * 256 + j * 32 + k];
        v1 = S[g * 65536 + d * 256 + j * 32 + k + 1];
    }
    __half2 h = __floats2half2_rn(v0, v1);
    g_wfrag[w] = *reinterpret_cast<u32*>(&h);
}

// one K=32 chunk: acc += W(frags @ wbuf) @ z(pair-rows kpb.. of zbase)
__device__ __forceinline__ void do_chunk(u32 wbuf, const u32* zbase, int kpb,
                                         float acc[4][4][4],
                                         int wd, int wp, int lane, int r, int c)
{
#pragma unroll
    for (int step = 0; step < 2; step++) {
        u32 a[4][4];
#pragma unroll
        for (int mt = 0; mt < 4; mt++)
            lds128(a[mt], wbuf +
                   (u32)((((wd * 2 + step) * 4 + mt) * 32 + lane) * 16));
        const int prow = kpb + step * 8 + c;
        const u32* zrow = zbase + prow * 64;
        const int nb = wp * 32 + r;
        u32 bf[4][2];
#pragma unroll
        for (int nt = 0; nt < 4; nt++) {
            const int col = nb + (((nt ^ c) & 3) << 3);
            bf[nt][0] = zrow[col];
            bf[nt][1] = zrow[4 * 64 + col];
        }
#pragma unroll
        for (int mt = 0; mt < 4; mt++)
#pragma unroll
            for (int nt = 0; nt < 4; nt++)
                mma16(acc[mt][nt], a[mt], bf[nt][0], bf[nt][1]);
    }
}

// ---------------- main fused kernel ----------------
__global__ void __launch_bounds__(256, 2)
lista_main(const float* __restrict__ x,
           const float* __restrict__ th,
           float* __restrict__ out)
{
    extern __shared__ u32 smem[];
    u32* Zkp = smem;

    const int tid  = threadIdx.x;
    const int lane = tid & 31;
    const int wid  = tid >> 5;
    const int wd   = wid & 3;               // dict group (64 d)
    const int wp   = wid >> 2;              // pixel group (32 px), 0..1
    const int r    = lane >> 2;
    const int c    = lane & 3;

    const int pix0 = blockIdx.x * 64;
    const int b    = pix0 >> 16;            // 65536 px per image
    const int hw0  = pix0 & 65535;

    const u32 smb = smem_u32(smem);

    // pre-stage chunks 0 and 1
    stage_chunk(smb + SBUF_OFF * 4, g_wfrag, tid);
    stage_chunk(smb + (SBUF_OFF + WBUF_WORDS) * 4, g_wfrag + WBUF_WORDS, tid);

    const float th0 = __ldg(th + 0), th1 = __ldg(th + 1);
    const float th2 = __ldg(th + 2), th3 = __ldg(th + 3);

    // ---- stage x into pair-rows 0..31 of the B region (XOR swizzle) ----
    {
        const float* xb = x + (size_t)b * 64 * 65536 + hw0;
#pragma unroll
        for (int e = 0; e < 8; e++) {
            const int idx = tid + e * 256;          // 2048 = 32 prow * 64 px
            const int px  = idx & 63;
            const int pr  = idx >> 6;               // 0..31
            const float v0 = __ldg(xb + (size_t)(2 * pr) * 65536 + px);
            const float v1 = __ldg(xb + (size_t)(2 * pr + 1) * 65536 + px);
            __half2 h = __floats2half2_rn(v0, v1);
            Zkp[BS_OFF + pr * 64 + (px ^ ((pr & 3) << 3))] =
                *reinterpret_cast<u32*>(&h);
        }
    }

    float acc[4][4][4];
#pragma unroll
    for (int mt = 0; mt < 4; mt++)
#pragma unroll
        for (int nt = 0; nt < 4; nt++)
#pragma unroll
            for (int q = 0; q < 4; q++) acc[mt][nt][q] = 0.0f;

#pragma unroll 1
    for (int i = 0; i < N_CHUNKS; i++) {
        if (i < N_CHUNKS - 1)
            asm volatile("cp.async.wait_group 1;" ::: "memory");
        else
            asm volatile("cp.async.wait_group 0;" ::: "memory");
        __syncthreads();        // chunk i landed; prior epilogue writes
                                // visible; buf (i+2)%3 free
        if (i + 2 < N_CHUNKS)
            stage_chunk(smb + (SBUF_OFF + ((i + 2) % 3) * WBUF_WORDS) * 4,
                        g_wfrag + (size_t)(i + 2) * WBUF_WORDS, tid);

        const u32* zbase = (i < 2) ? (Zkp + BS_OFF) : Zkp;   // We reads x
        const int  kpb   = (i < 2) ? i * 16 : ((i - 2) & 7) * 16;
        do_chunk(smb + (SBUF_OFF + (i % 3) * WBUF_WORDS) * 4,
                 zbase, kpb, acc, wd, wp, lane, r, c);

        // ---- iteration-boundary epilogues ----
        if (i == 1) {
            __syncthreads();    // all x reads done before B overwrites region
            const bool odd = (r & 1);
#pragma unroll
            for (int mt = 0; mt < 4; mt++) {
                const int prow_lo = wd * 32 + mt * 8 + (r >> 1);
                const int prow    = odd ? (prow_lo + 4) : prow_lo;
                const int swz     = (prow & 3) << 3;
#pragma unroll
                for (int nt = 0; nt < 4; nt++) {
                    __half2 hb0 = __floats2half2_rn(acc[mt][nt][0], acc[mt][nt][1]);
                    __half2 hb1 = __floats2half2_rn(acc[mt][nt][2], acc[mt][nt][3]);
                    const int wB = (mt * 4 + nt) * 2;
                    Zkp[BS_OFF + wB * 256 + tid]       = *reinterpret_cast<u32*>(&hb0);
                    Zkp[BS_OFF + (wB + 1) * 256 + tid] = *reinterpret_cast<u32*>(&hb1);
                    const float s0 = sshrink(acc[mt][nt][0], th0);
                    const float s1 = sshrink(acc[mt][nt][1], th0);
                    const float s2 = sshrink(acc[mt][nt][2], th0);
                    const float s3 = sshrink(acc[mt][nt][3], th0);
                    const float o0 = __shfl_xor_sync(0xffffffffu, s0, 4);
                    const float o1 = __shfl_xor_sync(0xffffffffu, s1, 4);
                    const float o2 = __shfl_xor_sync(0xffffffffu, s2, 4);
                    const float o3 = __shfl_xor_sync(0xffffffffu, s3, 4);
                    __half2 h0, h1;
                    if (!odd) { h0 = __floats2half2_rn(s0, o0);
                                h1 = __floats2half2_rn(s1, o1); }
                    else      { h0 = __floats2half2_rn(o2, s2);
                                h1 = __floats2half2_rn(o3, s3); }
                    const int col = (wp * 32 + nt * 8 + 2 * c) ^ swz;
                    uint2 v;
                    v.x = *reinterpret_cast<u32*>(&h0);
                    v.y = *reinterpret_cast<u32*>(&h1);
                    *reinterpret_cast<uint2*>(Zkp + prow * 64 + col) = v;
                    acc[mt][nt][0] = 0.0f; acc[mt][nt][1] = 0.0f;
                    acc[mt][nt][2] = 0.0f; acc[mt][nt][3] = 0.0f;
                }
            }
        } else if (i == 9 || i == 17) {
            __syncthreads();    // all z reads of chunk i done before overwrite
            const float theta = (i == 9) ? th1 : th2;
            const bool odd = (r & 1);
#pragma unroll
            for (int mt = 0; mt < 4; mt++) {
                const int prow_lo = wd * 32 + mt * 8 + (r >> 1);
                const int prow    = odd ? (prow_lo + 4) : prow_lo;
                const int swz     = (prow & 3) << 3;
#pragma unroll
                for (int nt = 0; nt < 4; nt++) {
                    const int wB = (mt * 4 + nt) * 2;
                    const u32 bw0 = Zkp[BS_OFF + wB * 256 + tid];
                    const u32 bw1 = Zkp[BS_OFF + (wB + 1) * 256 + tid];
                    const float2 b0 =
                        __half22float2(*reinterpret_cast<const __half2*>(&bw0));
                    const float2 b1 =
                        __half22float2(*reinterpret_cast<const __half2*>(&bw1));
                    const float s0 = sshrink(acc[mt][nt][0] + b0.x, theta);
                    const float s1 = sshrink(acc[mt][nt][1] + b0.y, theta);
                    const float s2 = sshrink(acc[mt][nt][2] + b1.x, theta);
                    const float s3 = sshrink(acc[mt][nt][3] + b1.y, theta);
                    const float o0 = __shfl_xor_sync(0xffffffffu, s0, 4);
                    const float o1 = __shfl_xor_sync(0xffffffffu, s1, 4);
                    const float o2 = __shfl_xor_sync(0xffffffffu, s2, 4);
                    const float o3 = __shfl_xor_sync(0xffffffffu, s3, 4);
                    __half2 h0, h1;
                    if (!odd) { h0 = __floats2half2_rn(s0, o0);
                                h1 = __floats2half2_rn(s1, o1); }
                    else      { h0 = __floats2half2_rn(o2, s2);
                                h1 = __floats2half2_rn(o3, s3); }
                    const int col = (wp * 32 + nt * 8 + 2 * c) ^ swz;
                    uint2 v;
                    v.x = *reinterpret_cast<u32*>(&h0);
                    v.y = *reinterpret_cast<u32*>(&h1);
                    *reinterpret_cast<uint2*>(Zkp + prow * 64 + col) = v;
                    acc[mt][nt][0] = 0.0f; acc[mt][nt][1] = 0.0f;
                    acc[mt][nt][2] = 0.0f; acc[mt][nt][3] = 0.0f;
                }
            }
        }
    }

    // ---- final epilogue: out = softshrink(acc + B, th3) -> gmem ----
    {
        float* ob = out + (size_t)b * 256 * 65536 + hw0;
#pragma unroll
        for (int mt = 0; mt < 4; mt++) {
            const int d0 = wd * 64 + mt * 16 + r;
#pragma unroll
            for (int nt = 0; nt < 4; nt++) {
                const int wB = (mt * 4 + nt) * 2;
                const u32 bw0 = Zkp[BS_OFF + wB * 256 + tid];
                const u32 bw1 = Zkp[BS_OFF + (wB + 1) * 256 + tid];
                const float2 b0 =
                    __half22float2(*reinterpret_cast<const __half2*>(&bw0));
                const float2 b1 =
                    __half22float2(*reinterpret_cast<const __half2*>(&bw1));
                const int px0 = wp * 32 + nt * 8 + 2 * c;
                *reinterpret_cast<float2*>(ob + (size_t)d0 * 65536 + px0) =
                    make_float2(sshrink(acc[mt][nt][0] + b0.x, th3),
                                sshrink(acc[mt][nt][1] + b0.y, th3));
                *reinterpret_cast<float2*>(ob + (size_t)(d0 + 8) * 65536 + px0) =
                    make_float2(sshrink(acc[mt][nt][2] + b1.x, th3),
                                sshrink(acc[mt][nt][3] + b1.y, th3));
            }
        }
    }
}

extern "C" void kernel_launch(void* const* d_in, const int* in_sizes, int n_in,
                              void* d_out, int out_size)
{
    (void)in_sizes; (void)n_in; (void)out_size;
    const float* x  = (const float*)d_in[0];
    const float* We = (const float*)d_in[1];
    const float* S  = (const float*)d_in[2];
    const float* th = (const float*)d_in[3];
    float* out      = (float*)d_out;

    lista_prep<<<(N_CHUNKS * WBUF_WORDS + 255) / 256, 256>>>(We, S);

    cudaFuncSetAttribute(lista_main, cudaFuncAttributeMaxDynamicSharedMemorySize,
                         SMEM_BYTES);
    lista_main<<<4096, 256, SMEM_BYTES>>>(x, th, out);
}

// round 12
// speedup vs baseline: 3.3760x; 1.2625x over previous
#include <cuda_runtime.h>
#include <cuda_fp16.h>
#include <cstdint>

typedef uint32_t u32;

// ------------------------------------------------------------------
// LISTA fused, mma.sync f16 (m16n8k16, fp32 accum), round 12.
//   B    = We @ x        (computed once, stored fp16 in smem)
//   z    = softshrink(B, th0)
//   3x:  z = softshrink(S[i] @ z + B, th[i+1])
//
// CTA = 64 px x 256 dict, 256 threads = 8 warps (4 dict x 2 px),
// warp tile 64d x 32px, 2 CTAs/SM.
// A (weight) fragments: pre-packed in gmem fragment order, loaded
// DIRECTLY gmem->registers (ld.global.nc.v4, L1/L2-resident) with
// one-step-ahead prefetch -> no cp.async, no weight smem, no
// per-chunk barriers. Crossbar carries only z B-fragments + epilogues.
// z in smem (k-pair half2, XOR swizzle); B in smem fp16 per-thread.
// ------------------------------------------------------------------

// smem u32-word map:
//   [0,    8192)  z: 128 pair-rows x 64 px (half2)
//   [8192,16384)  setup: x (32 pair-rows x 64) ; after GEMM0: B (fp16)
#define BS_OFF     8192
#define SMEM_BYTES (16384 * 4)           // 65536
#define N_CHUNKS   26                    // 2 We + 24 S, each K=32
#define WBUF_WORDS 4096

__device__ __align__(16) u32 g_wfrag[N_CHUNKS * WBUF_WORDS];

__device__ __forceinline__ float sshrink(float f, float th) {
    return f - fminf(fmaxf(f, -th), th);
}
__device__ __forceinline__ void mma16(float* c, const u32* a, u32 b0, u32 b1) {
    asm volatile(
        "mma.sync.aligned.m16n8k16.row.col.f32.f16.f16.f32 "
        "{%0,%1,%2,%3}, {%4,%5,%6,%7}, {%8,%9}, {%0,%1,%2,%3};"
        : "+f"(c[0]), "+f"(c[1]), "+f"(c[2]), "+f"(c[3])
        : "r"(a[0]), "r"(a[1]), "r"(a[2]), "r"(a[3]), "r"(b0), "r"(b1));
}
__device__ __forceinline__ void ldg4(u32* r, const u32* p) {
    asm volatile("ld.global.nc.v4.u32 {%0,%1,%2,%3}, [%4];"
                 : "=r"(r[0]), "=r"(r[1]), "=r"(r[2]), "=r"(r[3]) : "l"(p));
}

// ------------- prep: pack We/S into fp16 a-fragment order -------------
// word layout per K=32 chunk (4096 words): [wd 2][step 1][mt 2][lane 5][reg 2]
//   d = wd*64 + mt*16 + (reg&1)*8 + (lane>>2)
//   k = step*16 + (reg>>1)*8 + (lane&3)*2  (+0,+1 packed)
// chunk order = execution order: 0,1 = We k[0:32),k[32:64); 2.. = S.
__global__ void __launch_bounds__(256, 4)
lista_prep(const float* __restrict__ We, const float* __restrict__ S)
{
    const int w = blockIdx.x * 256 + threadIdx.x;
    if (w >= N_CHUNKS * WBUF_WORDS) return;
    const int chunk = w >> 12;
    const int rem   = w & 4095;
    const int wd    = rem >> 10;
    const int step  = (rem >> 9) & 1;
    const int mt    = (rem >> 7) & 3;
    const int lane  = (rem >> 2) & 31;
    const int reg   = rem & 3;
    const int d = wd * 64 + mt * 16 + (reg & 1) * 8 + (lane >> 2);
    const int k = step * 16 + (reg >> 1) * 8 + (lane & 3) * 2;
    float v0, v1;
    if (chunk < 2) {
        v0 = We[d * 64 + chunk * 32 + k];
        v1 = We[d * 64 + chunk * 32 + k + 1];
    } else {
        const int c = chunk - 2, g = c >> 3, j = c & 7;
        v0 = S[g * 65536 + d * 256 + j * 32 + k];
        v1 = S[g * 65536 + d * 256 + j * 32 + k + 1];
    }
    __half2 h = __floats2half2_rn(v0, v1);
    g_wfrag[w] = *reinterpret_cast<u32*>(&h);
}

// ---------------- main fused kernel ----------------
__global__ void __launch_bounds__(256, 2)
lista_main(const float* __restrict__ x,
           const float* __restrict__ th,
           float* __restrict__ out)
{
    extern __shared__ u32 smem[];
    u32* Zkp = smem;

    const int tid  = threadIdx.x;
    const int lane = tid & 31;
    const int wid  = tid >> 5;
    const int wd   = wid & 3;               // dict group (64 d)
    const int wp   = wid >> 2;              // pixel group (32 px), 0..1
    const int r    = lane >> 2;
    const int c    = lane & 3;

    const int pix0 = blockIdx.x * 64;
    const int b    = pix0 >> 16;            // 65536 px per image
    const int hw0  = pix0 & 65535;

    const float th0 = __ldg(th + 0), th1 = __ldg(th + 1);
    const float th2 = __ldg(th + 2), th3 = __ldg(th + 3);

    // per-warp fragment base in gmem: [wd][step][mt][lane][reg]
    const u32* gw = g_wfrag + (wd * 2) * 512 + lane * 4;

    // prefetch chunk 0, step 0 fragments
    u32 a0[16], a1[16];
#pragma unroll
    for (int mt = 0; mt < 4; mt++) ldg4(a0 + 4 * mt, gw + mt * 128);

    // ---- stage x into pair-rows 0..31 of the B region (XOR swizzle) ----
    {
        const float* xb = x + (size_t)b * 64 * 65536 + hw0;
#pragma unroll
        for (int e = 0; e < 8; e++) {
            const int idx = tid + e * 256;          // 2048 = 32 prow * 64 px
            const int px  = idx & 63;
            const int pr  = idx >> 6;               // 0..31
            const float v0 = __ldg(xb + (size_t)(2 * pr) * 65536 + px);
            const float v1 = __ldg(xb + (size_t)(2 * pr + 1) * 65536 + px);
            __half2 h = __floats2half2_rn(v0, v1);
            Zkp[BS_OFF + pr * 64 + (px ^ ((pr & 3) << 3))] =
                *reinterpret_cast<u32*>(&h);
        }
    }
    __syncthreads();                        // x visible to all warps

    float acc[4][4][4];
#pragma unroll
    for (int mt = 0; mt < 4; mt++)
#pragma unroll
        for (int nt = 0; nt < 4; nt++)
#pragma unroll
            for (int q = 0; q < 4; q++) acc[mt][nt][q] = 0.0f;

    const int nb = wp * 32 + r;

#pragma unroll 1
    for (int i = 0; i < N_CHUNKS; i++) {
        const u32* zbase = (i < 2) ? (Zkp + BS_OFF) : Zkp;   // We chunks read x
        const int  kpb   = (i < 2) ? i * 16 : ((i - 2) & 7) * 16;
        const u32* gwc   = gw + (size_t)i * WBUF_WORDS;

        // load step-1 fragments (consumed after step-0 MMAs)
#pragma unroll
        for (int mt = 0; mt < 4; mt++) ldg4(a1 + 4 * mt, gwc + 512 + mt * 128);

        // ---- step 0 ----
        {
            const u32* zrow = zbase + (kpb + c) * 64;
            u32 bf[4][2];
#pragma unroll
            for (int nt = 0; nt < 4; nt++) {
                const int col = nb + (((nt ^ c) & 3) << 3);
                bf[nt][0] = zrow[col];
                bf[nt][1] = zrow[4 * 64 + col];
            }
#pragma unroll
            for (int mt = 0; mt < 4; mt++)
#pragma unroll
                for (int nt = 0; nt < 4; nt++)
                    mma16(acc[mt][nt], a0 + 4 * mt, bf[nt][0], bf[nt][1]);
        }

        // prefetch next chunk's step-0 fragments
        if (i + 1 < N_CHUNKS) {
#pragma unroll
            for (int mt = 0; mt < 4; mt++)
                ldg4(a0 + 4 * mt, gwc + WBUF_WORDS + mt * 128);
        }

        // ---- step 1 ----
        {
            const u32* zrow = zbase + (kpb + 8 + c) * 64;
            u32 bf[4][2];
#pragma unroll
            for (int nt = 0; nt < 4; nt++) {
                const int col = nb + (((nt ^ c) & 3) << 3);
                bf[nt][0] = zrow[col];
                bf[nt][1] = zrow[4 * 64 + col];
            }
#pragma unroll
            for (int mt = 0; mt < 4; mt++)
#pragma unroll
                for (int nt = 0; nt < 4; nt++)
                    mma16(acc[mt][nt], a1 + 4 * mt, bf[nt][0], bf[nt][1]);
        }

        // ---- iteration-boundary epilogues ----
        if (i == 1) {
            __syncthreads();    // all x reads done before B overwrites region
            const bool odd = (r & 1);
#pragma unroll
            for (int mt = 0; mt < 4; mt++) {
                const int prow_lo = wd * 32 + mt * 8 + (r >> 1);
                const int prow    = odd ? (prow_lo + 4) : prow_lo;
                const int swz     = (prow & 3) << 3;
#pragma unroll
                for (int nt = 0; nt < 4; nt++) {
                    __half2 hb0 = __floats2half2_rn(acc[mt][nt][0], acc[mt][nt][1]);
                    __half2 hb1 = __floats2half2_rn(acc[mt][nt][2], acc[mt][nt][3]);
                    const int wB = (mt * 4 + nt) * 2;
                    Zkp[BS_OFF + wB * 256 + tid]       = *reinterpret_cast<u32*>(&hb0);
                    Zkp[BS_OFF + (wB + 1) * 256 + tid] = *reinterpret_cast<u32*>(&hb1);
                    const float s0 = sshrink(acc[mt][nt][0], th0);
                    const float s1 = sshrink(acc[mt][nt][1], th0);
                    const float s2 = sshrink(acc[mt][nt][2], th0);
                    const float s3 = sshrink(acc[mt][nt][3], th0);
                    const float o0 = __shfl_xor_sync(0xffffffffu, s0, 4);
                    const float o1 = __shfl_xor_sync(0xffffffffu, s1, 4);
                    const float o2 = __shfl_xor_sync(0xffffffffu, s2, 4);
                    const float o3 = __shfl_xor_sync(0xffffffffu, s3, 4);
                    __half2 h0, h1;
                    if (!odd) { h0 = __floats2half2_rn(s0, o0);
                                h1 = __floats2half2_rn(s1, o1); }
                    else      { h0 = __floats2half2_rn(o2, s2);
                                h1 = __floats2half2_rn(o3, s3); }
                    const int col = (wp * 32 + nt * 8 + 2 * c) ^ swz;
                    uint2 v;
                    v.x = *reinterpret_cast<u32*>(&h0);
                    v.y = *reinterpret_cast<u32*>(&h1);
                    *reinterpret_cast<uint2*>(Zkp + prow * 64 + col) = v;
                    acc[mt][nt][0] = 0.0f; acc[mt][nt][1] = 0.0f;
                    acc[mt][nt][2] = 0.0f; acc[mt][nt][3] = 0.0f;
                }
            }
            __syncthreads();    // z0 / B visible before next chunk reads
        } else if (i == 9 || i == 17) {
            __syncthreads();    // all z reads of this iteration done
            const float theta = (i == 9) ? th1 : th2;
            const bool odd = (r & 1);
#pragma unroll
            for (int mt = 0; mt < 4; mt++) {
                const int prow_lo = wd * 32 + mt * 8 + (r >> 1);
                const int prow    = odd ? (prow_lo + 4) : prow_lo;
                const int swz     = (prow & 3) << 3;
#pragma unroll
                for (int nt = 0; nt < 4; nt++) {
                    const int wB = (mt * 4 + nt) * 2;
                    const u32 bw0 = Zkp[BS_OFF + wB * 256 + tid];
                    const u32 bw1 = Zkp[BS_OFF + (wB + 1) * 256 + tid];
                    const float2 b0 =
                        __half22float2(*reinterpret_cast<const __half2*>(&bw0));
                    const float2 b1 =
                        __half22float2(*reinterpret_cast<const __half2*>(&bw1));
                    const float s0 = sshrink(acc[mt][nt][0] + b0.x, theta);
                    const float s1 = sshrink(acc[mt][nt][1] + b0.y, theta);
                    const float s2 = sshrink(acc[mt][nt][2] + b1.x, theta);
                    const float s3 = sshrink(acc[mt][nt][3] + b1.y, theta);
                    const float o0 = __shfl_xor_sync(0xffffffffu, s0, 4);
                    const float o1 = __shfl_xor_sync(0xffffffffu, s1, 4);
                    const float o2 = __shfl_xor_sync(0xffffffffu, s2, 4);
                    const float o3 = __shfl_xor_sync(0xffffffffu, s3, 4);
                    __half2 h0, h1;
                    if (!odd) { h0 = __floats2half2_rn(s0, o0);
                                h1 = __floats2half2_rn(s1, o1); }
                    else      { h0 = __floats2half2_rn(o2, s2);
                                h1 = __floats2half2_rn(o3, s3); }
                    const int col = (wp * 32 + nt * 8 + 2 * c) ^ swz;
                    uint2 v;
                    v.x = *reinterpret_cast<u32*>(&h0);
                    v.y = *reinterpret_cast<u32*>(&h1);
                    *reinterpret_cast<uint2*>(Zkp + prow * 64 + col) = v;
                    acc[mt][nt][0] = 0.0f; acc[mt][nt][1] = 0.0f;
                    acc[mt][nt][2] = 0.0f; acc[mt][nt][3] = 0.0f;
                }
            }
            __syncthreads();    // new z visible before next chunk reads
        }
    }

    // ---- final epilogue: out = softshrink(acc + B, th3) -> gmem ----
    {
        float* ob = out + (size_t)b * 256 * 65536 + hw0;
#pragma unroll
        for (int mt = 0; mt < 4; mt++) {
            const int d0 = wd * 64 + mt * 16 + r;
#pragma unroll
            for (int nt = 0; nt < 4; nt++) {
                const int wB = (mt * 4 + nt) * 2;
                const u32 bw0 = Zkp[BS_OFF + wB * 256 + tid];
                const u32 bw1 = Zkp[BS_OFF + (wB + 1) * 256 + tid];
                const float2 b0 =
                    __half22float2(*reinterpret_cast<const __half2*>(&bw0));
                const float2 b1 =
                    __half22float2(*reinterpret_cast<const __half2*>(&bw1));
                const int px0 = wp * 32 + nt * 8 + 2 * c;
                *reinterpret_cast<float2*>(ob + (size_t)d0 * 65536 + px0) =
                    make_float2(sshrink(acc[mt][nt][0] + b0.x, th3),
                                sshrink(acc[mt][nt][1] + b0.y, th3));
                *reinterpret_cast<float2*>(ob + (size_t)(d0 + 8) * 65536 + px0) =
                    make_float2(sshrink(acc[mt][nt][2] + b1.x, th3),
                                sshrink(acc[mt][nt][3] + b1.y, th3));
            }
        }
    }
}

extern "C" void kernel_launch(void* const* d_in, const int* in_sizes, int n_in,
                              void* d_out, int out_size)
{
    (void)in_sizes; (void)n_in; (void)out_size;
    const float* x  = (const float*)d_in[0];
    const float* We = (const float*)d_in[1];
    const float* S  = (const float*)d_in[2];
    const float* th = (const float*)d_in[3];
    float* out      = (float*)d_out;

    lista_prep<<<(N_CHUNKS * WBUF_WORDS + 255) / 256, 256>>>(We, S);

    cudaFuncSetAttribute(lista_main, cudaFuncAttributeMaxDynamicSharedMemorySize,
                         SMEM_BYTES);
    lista_main<<<4096, 256, SMEM_BYTES>>>(x, th, out);
}